// round 15
// baseline (speedup 1.0000x reference)
#include <cuda_runtime.h>
#include <cuda_bf16.h>
#include <cstdint>

#define Bb 8
#define Nn 4096
#define Dd 64
#define Ss 1024
#define Kk 32
#define RAD2 0.04f
#define NELEM 262144.0f   // B*32*S elements per channel for BN

// ---------------- scratch (device globals; no allocation allowed) ----------------
__device__ float g_featT[Bb * Nn * Dd];            // [b][n][c] point-major features
__device__ float g_centers[Bb * Ss * 3];           // [bs][3]
__device__ int   g_prog[Bb];                       // FPS progress (centers published)
__device__ int   g_tdone[Bb];                      // workers done transposing
__device__ float g_y0[Bb * Ss * Kk * 64];          // [bs][h][o]
__device__ float g_y1[Bb * Ss * Kk * 64];
__device__ float g_ymax[Bb * Ss * 128];            // per-(bs,c) max_h of y2 (pre-BN)
__device__ float g_ymin[Bb * Ss * 128];            // per-(bs,c) min_h of y2 (pre-BN)
__device__ float g_sum0[64],  g_sq0[64];
__device__ float g_sum1[64],  g_sq1[64];
__device__ float g_sum2[128], g_sq2[128];

__device__ __forceinline__ unsigned enc_mono(float f) {
    unsigned u = __float_as_uint(f);
    return (u & 0x80000000u) ? ~u : (u | 0x80000000u);
}
__device__ __forceinline__ float dec_mono(unsigned u) {
    return (u & 0x80000000u) ? __uint_as_float(u & 0x7fffffffu) : __uint_as_float(~u);
}

// ---------------- zero stats + progress ----------------
__global__ void zero_stats_kernel() {
    int t = threadIdx.x;
    if (t < 64)  { g_sum0[t] = 0.f; g_sq0[t] = 0.f; g_sum1[t] = 0.f; g_sq1[t] = 0.f; }
    if (t < 128) { g_sum2[t] = 0.f; g_sq2[t] = 0.f; }
    if (t < Bb)  { g_prog[t] = 0; g_tdone[t] = 0; }
}

// =====================================================================
// FUSED persistent kernel, grid = 148 (one wave, all co-resident):
//   blocks 0..7   : FPS producer (identical selection math)
//   blocks 8..147 : workers: transpose feat slice -> per-batch barrier;
//                   then per squad of 4 centers: wait progress ->
//                   ballquery (4 warps) -> conv0 GEMM + BN stats
// =====================================================================
__global__ __launch_bounds__(512) void fused_kernel(const float* __restrict__ pos,
                                                    const float* __restrict__ feat,
                                                    const float* __restrict__ w0,
                                                    const float* __restrict__ b0) {
    extern __shared__ __align__(16) float dyn[];
    float* tile = dyn;                       // [x:4096][y:4096][z:4096]
    int t = threadIdx.x;
    int warp = t >> 5, lane = t & 31;

    if (blockIdx.x < 8) {
        // ------------------- FPS producer -------------------
        float* sx = tile;
        float* sy = tile + Nn;
        float* sz = tile + 2 * Nn;
        __shared__ unsigned long long s_mv[2][16];

        int b = blockIdx.x;
        const float* P = pos + b * 3 * Nn;

        float px[8], py[8], pz[8], cum[8];
#pragma unroll
        for (int j = 0; j < 8; j++) {
            int n = t + 512 * j;
            px[j] = P[n];
            py[j] = P[Nn + n];
            pz[j] = P[2 * Nn + n];
            sx[n] = px[j]; sy[n] = py[j]; sz[n] = pz[j];
            cum[j] = 0.f;
        }

        const float NEG = -3.4e38f;
        if (t == 0) cum[0] = NEG;            // point 0 pre-selected
        __syncthreads();

        int cur = 0;
        for (int step = 1; step < Ss; step++) {
            int par = step & 1;
            float cx = sx[cur], cy = sy[cur], cz = sz[cur];

            if (t == 0) {
                float* c = &g_centers[(b * Ss + step - 1) * 3];
                c[0] = cx; c[1] = cy; c[2] = cz;
                if ((step & 31) == 0) {
                    __threadfence();
                    atomicExch(&g_prog[b], step);   // centers [0, step) published
                }
            }

            float m = NEG;
#pragma unroll
            for (int j = 0; j < 8; j++) {
                float dx = px[j] - cx, dy = py[j] - cy, dz = pz[j] - cz;
                float sqd = dx * dx + dy * dy + dz * dz;
                cum[j] = cum[j] + sqd;
                m = fmaxf(m, cum[j]);
            }

            unsigned um = enc_mono(m);
            unsigned uw = __reduce_max_sync(0xffffffffu, um);

            float mw = dec_mono(uw);
            int idx = 0x7fffffff;
#pragma unroll
            for (int j = 0; j < 8; j++)
                if (cum[j] == mw) idx = min(idx, t + 512 * j);
            idx = __reduce_min_sync(0xffffffffu, idx);

            if (lane == 0)
                s_mv[par][warp] = ((unsigned long long)uw << 32) | (unsigned)(~idx);
            __syncthreads();

            unsigned long long pk = s_mv[par][lane & 15];
            unsigned hi = (unsigned)(pk >> 32);
            unsigned lo = (unsigned)pk;
            unsigned mh = __reduce_max_sync(0xffffffffu, hi);
            unsigned ml = __reduce_max_sync(0xffffffffu, (hi == mh) ? lo : 0u);
            cur = (int)(~ml);

#pragma unroll
            for (int j = 0; j < 8; j++)
                if (cur == t + 512 * j) cum[j] = NEG;
        }

        if (t == 0) {
            float* c = &g_centers[(b * Ss + Ss - 1) * 3];
            c[0] = sx[cur]; c[1] = sy[cur]; c[2] = sz[cur];
            __threadfence();
            atomicExch(&g_prog[b], Ss);
        }
        return;
    }

    // ------------------- worker -------------------
    float* wT = dyn + 3 * Nn;                // 67*64 floats
    float* xs = dyn + 3 * Nn + 67 * 64;      // 8704 floats
    __shared__ int   sgi[128];
    __shared__ float sc3[12];
    __shared__ float ssum[64], ssq[64];

    int w  = blockIdx.x - 8;                 // 0..139
    int b  = w & 7;
    int wi = w >> 3;                         // 0..17
    int nb = (b < 4) ? 18 : 17;              // workers serving this batch

    const float* P = pos + b * 3 * Nn;
    for (int i = t; i < 3 * Nn; i += 512) tile[i] = P[i];
    for (int e = t; e < 67 * 64; e += 512) {
        int o = e & 63, i = e >> 6;
        wT[i * 64 + o] = w0[o * 67 + i];
    }
    if (t < 64) { ssum[t] = 0.f; ssq[t] = 0.f; }
    __syncthreads();

    // ---- cooperative feature transpose (hidden under FPS) ----
    const float* Fb = feat + b * (Dd * Nn);
    for (int tt = wi; tt < 128; tt += nb) {
        int n0 = tt * 32;
        for (int e = t; e < 2048; e += 512) {
            int c = e >> 5, i2 = e & 31;
            xs[i2 * 65 + c] = Fb[c * Nn + n0 + i2];      // coalesced read
        }
        __syncthreads();
        for (int e = t; e < 2048; e += 512) {
            int n = e >> 6, c = e & 63;
            g_featT[(b * Nn + n0 + n) * 64 + c] = xs[n * 65 + c];  // coalesced write
        }
        __syncthreads();
    }
    __threadfence();
    if (t == 0) {
        atomicAdd(&g_tdone[b], 1);
        while (*((volatile int*)&g_tdone[b]) < nb) __nanosleep(128);
    }
    __syncthreads();

    for (int squad = wi; squad < 256; squad += nb) {
        int s0 = squad * 4;

        if (t == 0) {
            while (*((volatile int*)&g_prog[b]) < s0 + 4) __nanosleep(64);
        }
        __syncthreads();

        // ---- ballquery: warp k handles center s0+k (identical logic) ----
        if (warp < 4) {
            int bs = b * Ss + s0 + warp;
            volatile float* C = (volatile float*)&g_centers[bs * 3];
            float cx = C[0], cy = C[1], cz = C[2];
            if (lane == 0) { sc3[warp * 3] = cx; sc3[warp * 3 + 1] = cy; sc3[warp * 3 + 2] = cz; }
            float csq = cx * cx + cy * cy + cz * cz;

            int cnt = 0, first = 0;
            int* G = &sgi[warp * 32];
            unsigned lanemask = (1u << lane) - 1u;
            for (int j0 = 0; j0 < Nn; j0 += 32) {
                int j = j0 + lane;
                float x = tile[j], y = tile[Nn + j], z = tile[2 * Nn + j];
                float dot = cx * x + cy * y + cz * z;
                float psq = x * x + y * y + z * z;
                float d = -2.0f * dot + csq + psq;
                bool ok = !(d > RAD2);
                unsigned m = __ballot_sync(0xffffffffu, ok);
                if (cnt == 0 && m) first = j0 + __ffs(m) - 1;
                int p = cnt + __popc(m & lanemask);
                if (ok && p < Kk) G[p] = j;
                cnt += __popc(m);
                if (cnt >= Kk) break;
            }
            for (int p = cnt + lane; p < Kk; p += 32) G[p] = first;
        }
        __syncthreads();

        // ---- gather 4 groups x 32 samples x 67 channels into xs ----
        for (int e = t; e < 4 * 32 * 67; e += 512) {
            int g = e / 2144;
            int r = e - g * 2144;
            int h = r / 67;
            int i = r - h * 67;
            int idx = sgi[g * 32 + h];
            float v;
            if (i < 3) v = tile[i * Nn + idx] - sc3[g * 3 + i];
            else       v = g_featT[(b * Nn + idx) * 64 + (i - 3)];
            xs[(g * 32 + h) * 68 + i] = v;
        }
        __syncthreads();

        // ---- conv0 GEMM: 512 threads, 4 groups ----
        int om = (t & 15) * 4;
        int hg = t >> 4;                     // 0..31
        int g  = hg >> 3;                    // 0..3
        int h4 = (hg & 7) * 4;

        float acc[4][4];
#pragma unroll
        for (int a = 0; a < 4; a++)
#pragma unroll
            for (int j = 0; j < 4; j++) acc[a][j] = 0.f;

        const float* xrow0 = &xs[(g * 32 + h4 + 0) * 68];
        const float* xrow1 = &xs[(g * 32 + h4 + 1) * 68];
        const float* xrow2 = &xs[(g * 32 + h4 + 2) * 68];
        const float* xrow3 = &xs[(g * 32 + h4 + 3) * 68];
        for (int i = 0; i < 67; i++) {
            float4 wv = *(const float4*)&wT[i * 64 + om];
            float xr0 = xrow0[i], xr1 = xrow1[i], xr2 = xrow2[i], xr3 = xrow3[i];
            acc[0][0] += xr0 * wv.x; acc[0][1] += xr0 * wv.y; acc[0][2] += xr0 * wv.z; acc[0][3] += xr0 * wv.w;
            acc[1][0] += xr1 * wv.x; acc[1][1] += xr1 * wv.y; acc[1][2] += xr1 * wv.z; acc[1][3] += xr1 * wv.w;
            acc[2][0] += xr2 * wv.x; acc[2][1] += xr2 * wv.y; acc[2][2] += xr2 * wv.z; acc[2][3] += xr2 * wv.w;
            acc[3][0] += xr3 * wv.x; acc[3][1] += xr3 * wv.y; acc[3][2] += xr3 * wv.z; acc[3][3] += xr3 * wv.w;
        }

        float4 bias4 = *(const float4*)&b0[om];
        float ls[4] = {0, 0, 0, 0}, lq[4] = {0, 0, 0, 0};
        int bs = b * Ss + s0 + g;
#pragma unroll
        for (int hh = 0; hh < 4; hh++) {
            float4 v;
            v.x = acc[hh][0] + bias4.x;
            v.y = acc[hh][1] + bias4.y;
            v.z = acc[hh][2] + bias4.z;
            v.w = acc[hh][3] + bias4.w;
            ls[0] += v.x; lq[0] += v.x * v.x;
            ls[1] += v.y; lq[1] += v.y * v.y;
            ls[2] += v.z; lq[2] += v.z * v.z;
            ls[3] += v.w; lq[3] += v.w * v.w;
            *(float4*)&g_y0[(bs * 32 + h4 + hh) * 64 + om] = v;
        }
#pragma unroll
        for (int j = 0; j < 4; j++) {
            atomicAdd(&ssum[om + j], ls[j]);
            atomicAdd(&ssq[om + j],  lq[j]);
        }
        __syncthreads();                     // protect xs/sgi for next task
    }

    if (t < 64) {
        atomicAdd(&g_sum0[t], ssum[t]);
        atomicAdd(&g_sq0[t],  ssq[t]);
    }
}

// ---------------- conv1: 64->64, 8 centers/block, 8x8 register tile -------------
__global__ __launch_bounds__(256, 2) void conv1_kernel(const float* __restrict__ w1,
                                                       const float* __restrict__ b1,
                                                       const float* __restrict__ gam0,
                                                       const float* __restrict__ bet0) {
    extern __shared__ __align__(16) float dsm1[];
    float* wT = dsm1;                         // 64*64 = 4096 floats
    float* xs = dsm1 + 4096;                  // 8*32*64 = 16384 floats
    __shared__ float ssum[64], ssq[64];
    __shared__ float s_scale[64], s_shift[64];

    int t = threadIdx.x;
    int bs0 = blockIdx.x * 8;
    for (int e = t; e < 64 * 64; e += 256) {
        int o = e & 63, i = e >> 6;
        wT[i * 64 + o] = w1[o * 64 + i];
    }
    if (t < 64) {
        ssum[t] = 0.f; ssq[t] = 0.f;
        float mean = g_sum0[t] * (1.0f / NELEM);
        float var  = g_sq0[t] * (1.0f / NELEM) - mean * mean;
        float s = gam0[t] * rsqrtf(var + 1e-5f);
        s_scale[t] = s;
        s_shift[t] = bet0[t] - mean * s;
    }
    __syncthreads();

    const float* Y = &g_y0[bs0 * 2048];
    for (int e = t; e < 16384; e += 256) {
        int i = e & 63;
        float v = Y[e] * s_scale[i] + s_shift[i];
        xs[e] = fmaxf(v, 0.f);
    }
    __syncthreads();

    int om = (t & 7) * 8;                     // 8 channels
    int hg = t >> 3;                          // 0..31
    int g  = hg >> 2;                         // 0..7 (center)
    int h8 = (hg & 3) * 8;                    // 0,8,16,24

    float acc[8][8];
#pragma unroll
    for (int a = 0; a < 8; a++)
#pragma unroll
        for (int j = 0; j < 8; j++) acc[a][j] = 0.f;

    const float* xbase = &xs[(g * 32 + h8) * 64];
    for (int i = 0; i < 64; i += 4) {
        float4 wa0 = *(const float4*)&wT[(i + 0) * 64 + om];
        float4 wb0 = *(const float4*)&wT[(i + 0) * 64 + om + 4];
        float4 wa1 = *(const float4*)&wT[(i + 1) * 64 + om];
        float4 wb1 = *(const float4*)&wT[(i + 1) * 64 + om + 4];
        float4 wa2 = *(const float4*)&wT[(i + 2) * 64 + om];
        float4 wb2 = *(const float4*)&wT[(i + 2) * 64 + om + 4];
        float4 wa3 = *(const float4*)&wT[(i + 3) * 64 + om];
        float4 wb3 = *(const float4*)&wT[(i + 3) * 64 + om + 4];
#pragma unroll
        for (int r = 0; r < 8; r++) {
            float4 xv = *(const float4*)&xbase[r * 64 + i];
            acc[r][0] += xv.x * wa0.x; acc[r][1] += xv.x * wa0.y; acc[r][2] += xv.x * wa0.z; acc[r][3] += xv.x * wa0.w;
            acc[r][4] += xv.x * wb0.x; acc[r][5] += xv.x * wb0.y; acc[r][6] += xv.x * wb0.z; acc[r][7] += xv.x * wb0.w;
            acc[r][0] += xv.y * wa1.x; acc[r][1] += xv.y * wa1.y; acc[r][2] += xv.y * wa1.z; acc[r][3] += xv.y * wa1.w;
            acc[r][4] += xv.y * wb1.x; acc[r][5] += xv.y * wb1.y; acc[r][6] += xv.y * wb1.z; acc[r][7] += xv.y * wb1.w;
            acc[r][0] += xv.z * wa2.x; acc[r][1] += xv.z * wa2.y; acc[r][2] += xv.z * wa2.z; acc[r][3] += xv.z * wa2.w;
            acc[r][4] += xv.z * wb2.x; acc[r][5] += xv.z * wb2.y; acc[r][6] += xv.z * wb2.z; acc[r][7] += xv.z * wb2.w;
            acc[r][0] += xv.w * wa3.x; acc[r][1] += xv.w * wa3.y; acc[r][2] += xv.w * wa3.z; acc[r][3] += xv.w * wa3.w;
            acc[r][4] += xv.w * wb3.x; acc[r][5] += xv.w * wb3.y; acc[r][6] += xv.w * wb3.z; acc[r][7] += xv.w * wb3.w;
        }
    }

    float4 ba = *(const float4*)&b1[om];
    float4 bb = *(const float4*)&b1[om + 4];
    float ls[8] = {0,0,0,0,0,0,0,0}, lq[8] = {0,0,0,0,0,0,0,0};
    int bs = bs0 + g;
#pragma unroll
    for (int hh = 0; hh < 8; hh++) {
        float4 v0, v1;
        v0.x = acc[hh][0] + ba.x; v0.y = acc[hh][1] + ba.y;
        v0.z = acc[hh][2] + ba.z; v0.w = acc[hh][3] + ba.w;
        v1.x = acc[hh][4] + bb.x; v1.y = acc[hh][5] + bb.y;
        v1.z = acc[hh][6] + bb.z; v1.w = acc[hh][7] + bb.w;
        ls[0] += v0.x; lq[0] += v0.x * v0.x;
        ls[1] += v0.y; lq[1] += v0.y * v0.y;
        ls[2] += v0.z; lq[2] += v0.z * v0.z;
        ls[3] += v0.w; lq[3] += v0.w * v0.w;
        ls[4] += v1.x; lq[4] += v1.x * v1.x;
        ls[5] += v1.y; lq[5] += v1.y * v1.y;
        ls[6] += v1.z; lq[6] += v1.z * v1.z;
        ls[7] += v1.w; lq[7] += v1.w * v1.w;
        float* dst = &g_y1[(bs * 32 + h8 + hh) * 64 + om];
        *(float4*)dst = v0;
        *(float4*)(dst + 4) = v1;
    }
#pragma unroll
    for (int j = 0; j < 8; j++) {
        atomicAdd(&ssum[om + j], ls[j]);
        atomicAdd(&ssq[om + j],  lq[j]);
    }
    __syncthreads();
    if (t < 64) {
        atomicAdd(&g_sum1[t], ssum[t]);
        atomicAdd(&g_sq1[t],  ssq[t]);
    }
}

// ---------------- conv2: 64->128, (8 centers x 64 out)/block, 8x8 tile ----------
// Outputs only: BN2 stats + per-(bs,channel) max/min of y2 over h.
__global__ __launch_bounds__(256, 2) void conv2_kernel(const float* __restrict__ w2,
                                                       const float* __restrict__ b2,
                                                       const float* __restrict__ gam1,
                                                       const float* __restrict__ bet1) {
    extern __shared__ __align__(16) float dsm2[];
    float* wT = dsm2;                         // 64*64 floats (half panel)
    float* xs = dsm2 + 4096;                  // 8*32*64 = 16384 floats
    __shared__ float ssum[64], ssq[64];
    __shared__ float s_scale[64], s_shift[64];
    __shared__ unsigned smax[512], smin[512]; // [g 0..7][c 0..63] monotone-encoded

    int t = threadIdx.x;
    int half = blockIdx.x & 1;
    int bs0  = (blockIdx.x >> 1) * 8;
    int ocb  = half * 64;

    for (int e = t; e < 64 * 64; e += 256) {
        int o = e & 63, i = e >> 6;
        wT[i * 64 + o] = w2[(ocb + o) * 64 + i];
    }
    if (t < 64) { ssum[t] = 0.f; ssq[t] = 0.f; }
    smax[t] = 0u; smax[t + 256] = 0u;
    smin[t] = 0xffffffffu; smin[t + 256] = 0xffffffffu;
    if (t < 64) {
        float mean = g_sum1[t] * (1.0f / NELEM);
        float var  = g_sq1[t] * (1.0f / NELEM) - mean * mean;
        float s = gam1[t] * rsqrtf(var + 1e-5f);
        s_scale[t] = s;
        s_shift[t] = bet1[t] - mean * s;
    }
    __syncthreads();

    const float* Y = &g_y1[bs0 * 2048];
    for (int e = t; e < 16384; e += 256) {
        int i = e & 63;
        float v = Y[e] * s_scale[i] + s_shift[i];
        xs[e] = fmaxf(v, 0.f);
    }
    __syncthreads();

    int om = (t & 7) * 8;                     // 8 channels within half
    int hg = t >> 3;                          // 0..31
    int g  = hg >> 2;                         // 0..7 (center)
    int h8 = (hg & 3) * 8;                    // 0,8,16,24

    float acc[8][8];
#pragma unroll
    for (int a = 0; a < 8; a++)
#pragma unroll
        for (int j = 0; j < 8; j++) acc[a][j] = 0.f;

    const float* xbase = &xs[(g * 32 + h8) * 64];
    for (int i = 0; i < 64; i += 4) {
        float4 wa0 = *(const float4*)&wT[(i + 0) * 64 + om];
        float4 wb0 = *(const float4*)&wT[(i + 0) * 64 + om + 4];
        float4 wa1 = *(const float4*)&wT[(i + 1) * 64 + om];
        float4 wb1 = *(const float4*)&wT[(i + 1) * 64 + om + 4];
        float4 wa2 = *(const float4*)&wT[(i + 2) * 64 + om];
        float4 wb2 = *(const float4*)&wT[(i + 2) * 64 + om + 4];
        float4 wa3 = *(const float4*)&wT[(i + 3) * 64 + om];
        float4 wb3 = *(const float4*)&wT[(i + 3) * 64 + om + 4];
#pragma unroll
        for (int r = 0; r < 8; r++) {
            float4 xv = *(const float4*)&xbase[r * 64 + i];
            acc[r][0] += xv.x * wa0.x; acc[r][1] += xv.x * wa0.y; acc[r][2] += xv.x * wa0.z; acc[r][3] += xv.x * wa0.w;
            acc[r][4] += xv.x * wb0.x; acc[r][5] += xv.x * wb0.y; acc[r][6] += xv.x * wb0.z; acc[r][7] += xv.x * wb0.w;
            acc[r][0] += xv.y * wa1.x; acc[r][1] += xv.y * wa1.y; acc[r][2] += xv.y * wa1.z; acc[r][3] += xv.y * wa1.w;
            acc[r][4] += xv.y * wb1.x; acc[r][5] += xv.y * wb1.y; acc[r][6] += xv.y * wb1.z; acc[r][7] += xv.y * wb1.w;
            acc[r][0] += xv.z * wa2.x; acc[r][1] += xv.z * wa2.y; acc[r][2] += xv.z * wa2.z; acc[r][3] += xv.z * wa2.w;
            acc[r][4] += xv.z * wb2.x; acc[r][5] += xv.z * wb2.y; acc[r][6] += xv.z * wb2.z; acc[r][7] += xv.z * wb2.w;
            acc[r][0] += xv.w * wa3.x; acc[r][1] += xv.w * wa3.y; acc[r][2] += xv.w * wa3.z; acc[r][3] += xv.w * wa3.w;
            acc[r][4] += xv.w * wb3.x; acc[r][5] += xv.w * wb3.y; acc[r][6] += xv.w * wb3.z; acc[r][7] += xv.w * wb3.w;
        }
    }

    float4 ba = *(const float4*)&b2[ocb + om];
    float4 bb = *(const float4*)&b2[ocb + om + 4];
    float bias8[8] = {ba.x, ba.y, ba.z, ba.w, bb.x, bb.y, bb.z, bb.w};
    float ls[8] = {0,0,0,0,0,0,0,0}, lq[8] = {0,0,0,0,0,0,0,0};
    float vmx[8], vmn[8];
#pragma unroll
    for (int j = 0; j < 8; j++) { vmx[j] = -3.4e38f; vmn[j] = 3.4e38f; }
#pragma unroll
    for (int hh = 0; hh < 8; hh++) {
#pragma unroll
        for (int j = 0; j < 8; j++) {
            float v = acc[hh][j] + bias8[j];
            ls[j] += v; lq[j] += v * v;
            vmx[j] = fmaxf(vmx[j], v);
            vmn[j] = fminf(vmn[j], v);
        }
    }
#pragma unroll
    for (int j = 0; j < 8; j++) {
        atomicAdd(&ssum[om + j], ls[j]);
        atomicAdd(&ssq[om + j],  lq[j]);
        atomicMax(&smax[g * 64 + om + j], enc_mono(vmx[j]));
        atomicMin(&smin[g * 64 + om + j], enc_mono(vmn[j]));
    }
    __syncthreads();
    if (t < 64) {
        atomicAdd(&g_sum2[ocb + t], ssum[t]);
        atomicAdd(&g_sq2[ocb + t],  ssq[t]);
    }
    // write per-center channel max/min: entry e -> (g=e>>6, c=e&63)
#pragma unroll
    for (int e = t; e < 512; e += 256) {
        int gg = e >> 6, cc = e & 63;
        int bs = bs0 + gg;
        g_ymax[bs * 128 + ocb + cc] = dec_mono(smax[gg * 64 + cc]);
        g_ymin[bs * 128 + ocb + cc] = dec_mono(smin[gg * 64 + cc]);
    }
}

// ---------------- final: BN2 on pooled extrema + relu + poscopy -----------------
__global__ __launch_bounds__(256) void finalpool_kernel(float* __restrict__ out,
                                                        const float* __restrict__ gam2,
                                                        const float* __restrict__ bet2) {
    __shared__ float s_sc[128], s_sh[128];
    int t = threadIdx.x;
    if (t < 128) {
        float mean = g_sum2[t] * (1.0f / NELEM);
        float var  = g_sq2[t] * (1.0f / NELEM) - mean * mean;
        float s = gam2[t] * rsqrtf(var + 1e-5f);
        s_sc[t] = s;
        s_sh[t] = bet2[t] - mean * s;
    }
    __syncthreads();

    int gwarp = (blockIdx.x * blockDim.x + t) >> 5;   // bs
    int lane = t & 31;
    {
        int bs = gwarp;
        int b = bs >> 10, s = bs & 1023;
        const float* MX = &g_ymax[bs * 128];
        const float* MN = &g_ymin[bs * 128];
        float* F = out + Bb * 3 * Ss + b * 128 * Ss + s;
#pragma unroll
        for (int j = 0; j < 4; j++) {
            int c = lane + 32 * j;
            float scl = s_sc[c], sft = s_sh[c];
            float y = (scl >= 0.f) ? MX[c] : MN[c];
            float v = fmaxf(y * scl + sft, 0.f);
            F[c * Ss] = v;
        }
    }

    // fused poscopy: first 24576 global threads copy pos_out
    int e = blockIdx.x * blockDim.x + t;
    if (e < Bb * 3 * Ss) {
        int b2_ = e / (3 * Ss);
        int r = e - b2_ * (3 * Ss);
        int c = r / Ss;
        int s2 = r - c * Ss;
        out[e] = g_centers[(b2_ * Ss + s2) * 3 + c];
    }
}

// ---------------- launch --------------------------------------------------------
extern "C" void kernel_launch(void* const* d_in, const int* in_sizes, int n_in,
                              void* d_out, int out_size) {
    const float* pos  = (const float*)d_in[0];
    const float* feat = (const float*)d_in[1];
    const float* w0   = (const float*)d_in[2];
    const float* b0   = (const float*)d_in[3];
    const float* g0   = (const float*)d_in[4];
    const float* be0  = (const float*)d_in[5];
    const float* w1   = (const float*)d_in[6];
    const float* b1   = (const float*)d_in[7];
    const float* g1   = (const float*)d_in[8];
    const float* be1  = (const float*)d_in[9];
    const float* w2   = (const float*)d_in[10];
    const float* b2   = (const float*)d_in[11];
    const float* g2   = (const float*)d_in[12];
    const float* be2  = (const float*)d_in[13];
    float* out = (float*)d_out;

    const int FUSED_DYN = (3 * Nn + 67 * 64 + 4 * 32 * 68) * (int)sizeof(float); // 101120
    const int CV_DYN = (64 * 64 + 8 * 32 * 64) * (int)sizeof(float);             // 81920
    cudaFuncSetAttribute(fused_kernel, cudaFuncAttributeMaxDynamicSharedMemorySize, FUSED_DYN);
    cudaFuncSetAttribute(conv1_kernel, cudaFuncAttributeMaxDynamicSharedMemorySize, CV_DYN);
    cudaFuncSetAttribute(conv2_kernel, cudaFuncAttributeMaxDynamicSharedMemorySize, CV_DYN);

    zero_stats_kernel<<<1, 128>>>();                              // 1
    fused_kernel<<<148, 512, FUSED_DYN>>>(pos, feat, w0, b0);     // 2
    conv1_kernel<<<Bb * Ss / 8, 256, CV_DYN>>>(w1, b1, g0, be0);  // 3
    conv2_kernel<<<Bb * Ss / 4, 256, CV_DYN>>>(w2, b2, g1, be1);  // 4
    finalpool_kernel<<<Bb * Ss / 8, 256>>>(out, g2, be2);         // 5
}

// round 16
// speedup vs baseline: 1.0952x; 1.0952x over previous
#include <cuda_runtime.h>
#include <cuda_bf16.h>
#include <cstdint>

#define Bb 8
#define Nn 4096
#define Dd 64
#define Ss 1024
#define Kk 32
#define RAD2 0.04f
#define NELEM 262144.0f   // B*32*S elements per channel for BN

// ---------------- scratch (device globals; no allocation allowed) ----------------
__device__ float g_featT[Bb * Nn * Dd];            // [b][n][c] point-major features
__device__ float g_centers[Bb * Ss * 3];           // [bs][3]
__device__ int   g_prog[Bb];                       // FPS progress (centers published)
__device__ int   g_tdone[Bb];                      // workers done transposing
__device__ float g_y0[Bb * Ss * Kk * 64];          // [bs][h][o]
__device__ float g_y1[Bb * Ss * Kk * 64];
__device__ float g_ymax[Bb * Ss * 128];            // per-(bs,c) max_h of y2 (pre-BN)
__device__ float g_ymin[Bb * Ss * 128];            // per-(bs,c) min_h of y2 (pre-BN)
__device__ float g_sum0[64],  g_sq0[64];
__device__ float g_sum1[64],  g_sq1[64];
__device__ float g_sum2[128], g_sq2[128];

__device__ __forceinline__ unsigned enc_mono(float f) {
    unsigned u = __float_as_uint(f);
    return (u & 0x80000000u) ? ~u : (u | 0x80000000u);
}
__device__ __forceinline__ float dec_mono(unsigned u) {
    return (u & 0x80000000u) ? __uint_as_float(u & 0x7fffffffu) : __uint_as_float(~u);
}

// ---------------- zero stats + progress ----------------
__global__ void zero_stats_kernel() {
    int t = threadIdx.x;
    if (t < 64)  { g_sum0[t] = 0.f; g_sq0[t] = 0.f; g_sum1[t] = 0.f; g_sq1[t] = 0.f; }
    if (t < 128) { g_sum2[t] = 0.f; g_sq2[t] = 0.f; }
    if (t < Bb)  { g_prog[t] = 0; g_tdone[t] = 0; }
}

// =====================================================================
// FUSED persistent kernel, grid = 148 (one wave, all co-resident):
//   blocks 0..7   : FPS producer (identical selection math)
//   blocks 8..147 : workers: transpose feat slice -> per-batch barrier;
//                   then per squad of 4 centers: wait progress ->
//                   ballquery (4 warps) -> conv0 GEMM + BN stats
// =====================================================================
__global__ __launch_bounds__(512) void fused_kernel(const float* __restrict__ pos,
                                                    const float* __restrict__ feat,
                                                    const float* __restrict__ w0,
                                                    const float* __restrict__ b0) {
    extern __shared__ __align__(16) float dyn[];
    float* tile = dyn;                       // [x:4096][y:4096][z:4096]
    int t = threadIdx.x;
    int warp = t >> 5, lane = t & 31;

    if (blockIdx.x < 8) {
        // ------------------- FPS producer -------------------
        float* sx = tile;
        float* sy = tile + Nn;
        float* sz = tile + 2 * Nn;
        __shared__ unsigned long long s_mv[2][16];

        int b = blockIdx.x;
        const float* P = pos + b * 3 * Nn;

        float px[8], py[8], pz[8], cum[8];
#pragma unroll
        for (int j = 0; j < 8; j++) {
            int n = t + 512 * j;
            px[j] = P[n];
            py[j] = P[Nn + n];
            pz[j] = P[2 * Nn + n];
            sx[n] = px[j]; sy[n] = py[j]; sz[n] = pz[j];
            cum[j] = 0.f;
        }

        const float NEG = -3.4e38f;
        if (t == 0) cum[0] = NEG;            // point 0 pre-selected
        __syncthreads();

        int cur = 0;
        for (int step = 1; step < Ss; step++) {
            int par = step & 1;
            float cx = sx[cur], cy = sy[cur], cz = sz[cur];

            if (t == 0) {
                float* c = &g_centers[(b * Ss + step - 1) * 3];
                c[0] = cx; c[1] = cy; c[2] = cz;
                if ((step & 31) == 0) {
                    __threadfence();
                    atomicExch(&g_prog[b], step);   // centers [0, step) published
                }
            }

            float m = NEG;
#pragma unroll
            for (int j = 0; j < 8; j++) {
                float dx = px[j] - cx, dy = py[j] - cy, dz = pz[j] - cz;
                float sqd = dx * dx + dy * dy + dz * dz;
                cum[j] = cum[j] + sqd;
                m = fmaxf(m, cum[j]);
            }

            unsigned um = enc_mono(m);
            unsigned uw = __reduce_max_sync(0xffffffffu, um);

            float mw = dec_mono(uw);
            int idx = 0x7fffffff;
#pragma unroll
            for (int j = 0; j < 8; j++)
                if (cum[j] == mw) idx = min(idx, t + 512 * j);
            idx = __reduce_min_sync(0xffffffffu, idx);

            if (lane == 0)
                s_mv[par][warp] = ((unsigned long long)uw << 32) | (unsigned)(~idx);
            __syncthreads();

            unsigned long long pk = s_mv[par][lane & 15];
            unsigned hi = (unsigned)(pk >> 32);
            unsigned lo = (unsigned)pk;
            unsigned mh = __reduce_max_sync(0xffffffffu, hi);
            unsigned ml = __reduce_max_sync(0xffffffffu, (hi == mh) ? lo : 0u);
            cur = (int)(~ml);

#pragma unroll
            for (int j = 0; j < 8; j++)
                if (cur == t + 512 * j) cum[j] = NEG;
        }

        if (t == 0) {
            float* c = &g_centers[(b * Ss + Ss - 1) * 3];
            c[0] = sx[cur]; c[1] = sy[cur]; c[2] = sz[cur];
            __threadfence();
            atomicExch(&g_prog[b], Ss);
        }
        return;
    }

    // ------------------- worker -------------------
    float* wT = dyn + 3 * Nn;                // 67*64 floats
    float* xs = dyn + 3 * Nn + 67 * 64;      // 8704 floats
    __shared__ int   sgi[128];
    __shared__ float sc3[12];
    __shared__ float ssum[64], ssq[64];

    int w  = blockIdx.x - 8;                 // 0..139
    int b  = w & 7;
    int wi = w >> 3;                         // 0..17
    int nb = (b < 4) ? 18 : 17;              // workers serving this batch

    const float* P = pos + b * 3 * Nn;
    for (int i = t; i < 3 * Nn; i += 512) tile[i] = P[i];
    for (int e = t; e < 67 * 64; e += 512) {
        int o = e & 63, i = e >> 6;
        wT[i * 64 + o] = w0[o * 67 + i];
    }
    if (t < 64) { ssum[t] = 0.f; ssq[t] = 0.f; }
    __syncthreads();

    // ---- cooperative feature transpose (hidden under FPS) ----
    const float* Fb = feat + b * (Dd * Nn);
    for (int tt = wi; tt < 128; tt += nb) {
        int n0 = tt * 32;
        for (int e = t; e < 2048; e += 512) {
            int c = e >> 5, i2 = e & 31;
            xs[i2 * 65 + c] = Fb[c * Nn + n0 + i2];      // coalesced read
        }
        __syncthreads();
        for (int e = t; e < 2048; e += 512) {
            int n = e >> 6, c = e & 63;
            g_featT[(b * Nn + n0 + n) * 64 + c] = xs[n * 65 + c];  // coalesced write
        }
        __syncthreads();
    }
    __threadfence();
    if (t == 0) {
        atomicAdd(&g_tdone[b], 1);
        while (*((volatile int*)&g_tdone[b]) < nb) __nanosleep(128);
    }
    __syncthreads();

    for (int squad = wi; squad < 256; squad += nb) {
        int s0 = squad * 4;

        if (t == 0) {
            while (*((volatile int*)&g_prog[b]) < s0 + 4) __nanosleep(64);
        }
        __syncthreads();

        // ---- ballquery: warp k handles center s0+k (identical logic) ----
        if (warp < 4) {
            int bs = b * Ss + s0 + warp;
            volatile float* C = (volatile float*)&g_centers[bs * 3];
            float cx = C[0], cy = C[1], cz = C[2];
            if (lane == 0) { sc3[warp * 3] = cx; sc3[warp * 3 + 1] = cy; sc3[warp * 3 + 2] = cz; }
            float csq = cx * cx + cy * cy + cz * cz;

            int cnt = 0, first = 0;
            int* G = &sgi[warp * 32];
            unsigned lanemask = (1u << lane) - 1u;
            for (int j0 = 0; j0 < Nn; j0 += 32) {
                int j = j0 + lane;
                float x = tile[j], y = tile[Nn + j], z = tile[2 * Nn + j];
                float dot = cx * x + cy * y + cz * z;
                float psq = x * x + y * y + z * z;
                float d = -2.0f * dot + csq + psq;
                bool ok = !(d > RAD2);
                unsigned m = __ballot_sync(0xffffffffu, ok);
                if (cnt == 0 && m) first = j0 + __ffs(m) - 1;
                int p = cnt + __popc(m & lanemask);
                if (ok && p < Kk) G[p] = j;
                cnt += __popc(m);
                if (cnt >= Kk) break;
            }
            for (int p = cnt + lane; p < Kk; p += 32) G[p] = first;
        }
        __syncthreads();

        // ---- gather 4 groups x 32 samples x 67 channels into xs ----
        for (int e = t; e < 4 * 32 * 67; e += 512) {
            int g = e / 2144;
            int r = e - g * 2144;
            int h = r / 67;
            int i = r - h * 67;
            int idx = sgi[g * 32 + h];
            float v;
            if (i < 3) v = tile[i * Nn + idx] - sc3[g * 3 + i];
            else       v = g_featT[(b * Nn + idx) * 64 + (i - 3)];
            xs[(g * 32 + h) * 68 + i] = v;
        }
        __syncthreads();

        // ---- conv0 GEMM: 512 threads, 4 groups ----
        int om = (t & 15) * 4;
        int hg = t >> 4;                     // 0..31
        int g  = hg >> 3;                    // 0..3
        int h4 = (hg & 7) * 4;

        float acc[4][4];
#pragma unroll
        for (int a = 0; a < 4; a++)
#pragma unroll
            for (int j = 0; j < 4; j++) acc[a][j] = 0.f;

        const float* xrow0 = &xs[(g * 32 + h4 + 0) * 68];
        const float* xrow1 = &xs[(g * 32 + h4 + 1) * 68];
        const float* xrow2 = &xs[(g * 32 + h4 + 2) * 68];
        const float* xrow3 = &xs[(g * 32 + h4 + 3) * 68];
        for (int i = 0; i < 67; i++) {
            float4 wv = *(const float4*)&wT[i * 64 + om];
            float xr0 = xrow0[i], xr1 = xrow1[i], xr2 = xrow2[i], xr3 = xrow3[i];
            acc[0][0] += xr0 * wv.x; acc[0][1] += xr0 * wv.y; acc[0][2] += xr0 * wv.z; acc[0][3] += xr0 * wv.w;
            acc[1][0] += xr1 * wv.x; acc[1][1] += xr1 * wv.y; acc[1][2] += xr1 * wv.z; acc[1][3] += xr1 * wv.w;
            acc[2][0] += xr2 * wv.x; acc[2][1] += xr2 * wv.y; acc[2][2] += xr2 * wv.z; acc[2][3] += xr2 * wv.w;
            acc[3][0] += xr3 * wv.x; acc[3][1] += xr3 * wv.y; acc[3][2] += xr3 * wv.z; acc[3][3] += xr3 * wv.w;
        }

        float4 bias4 = *(const float4*)&b0[om];
        float ls[4] = {0, 0, 0, 0}, lq[4] = {0, 0, 0, 0};
        int bs = b * Ss + s0 + g;
#pragma unroll
        for (int hh = 0; hh < 4; hh++) {
            float4 v;
            v.x = acc[hh][0] + bias4.x;
            v.y = acc[hh][1] + bias4.y;
            v.z = acc[hh][2] + bias4.z;
            v.w = acc[hh][3] + bias4.w;
            ls[0] += v.x; lq[0] += v.x * v.x;
            ls[1] += v.y; lq[1] += v.y * v.y;
            ls[2] += v.z; lq[2] += v.z * v.z;
            ls[3] += v.w; lq[3] += v.w * v.w;
            *(float4*)&g_y0[(bs * 32 + h4 + hh) * 64 + om] = v;
        }
#pragma unroll
        for (int j = 0; j < 4; j++) {
            atomicAdd(&ssum[om + j], ls[j]);
            atomicAdd(&ssq[om + j],  lq[j]);
        }
        __syncthreads();                     // protect xs/sgi for next task
    }

    if (t < 64) {
        atomicAdd(&g_sum0[t], ssum[t]);
        atomicAdd(&g_sq0[t],  ssq[t]);
    }
}

// ---------------- conv1: 64->64, 4 centers/block, 8x4 register tile -------------
__global__ __launch_bounds__(256, 4) void conv1_kernel(const float* __restrict__ w1,
                                                       const float* __restrict__ b1,
                                                       const float* __restrict__ gam0,
                                                       const float* __restrict__ bet0) {
    extern __shared__ __align__(16) float dsm1[];
    float* wT = dsm1;                         // 64*64 = 4096 floats
    float* xs = dsm1 + 4096;                  // 4*32*64 = 8192 floats
    __shared__ float ssum[64], ssq[64];
    __shared__ float s_scale[64], s_shift[64];

    int t = threadIdx.x;
    int bs0 = blockIdx.x * 4;
    for (int e = t; e < 64 * 64; e += 256) {
        int o = e & 63, i = e >> 6;
        wT[i * 64 + o] = w1[o * 64 + i];
    }
    if (t < 64) {
        ssum[t] = 0.f; ssq[t] = 0.f;
        float mean = g_sum0[t] * (1.0f / NELEM);
        float var  = g_sq0[t] * (1.0f / NELEM) - mean * mean;
        float s = gam0[t] * rsqrtf(var + 1e-5f);
        s_scale[t] = s;
        s_shift[t] = bet0[t] - mean * s;
    }
    __syncthreads();

    const float* Y = &g_y0[bs0 * 2048];
    for (int e = t; e < 8192; e += 256) {
        int i = e & 63;
        float v = Y[e] * s_scale[i] + s_shift[i];
        xs[e] = fmaxf(v, 0.f);
    }
    __syncthreads();

    int om = (t & 15) * 4;
    int hg = t >> 4;                          // 0..15
    int g  = hg >> 2;                         // 0..3 (center)
    int h8 = (hg & 3) * 8;                    // 0,8,16,24

    float acc[8][4];
#pragma unroll
    for (int a = 0; a < 8; a++)
#pragma unroll
        for (int j = 0; j < 4; j++) acc[a][j] = 0.f;

    const float* xbase = &xs[(g * 32 + h8) * 64];
    for (int i = 0; i < 64; i += 4) {
        float4 wv0 = *(const float4*)&wT[(i + 0) * 64 + om];
        float4 wv1 = *(const float4*)&wT[(i + 1) * 64 + om];
        float4 wv2 = *(const float4*)&wT[(i + 2) * 64 + om];
        float4 wv3 = *(const float4*)&wT[(i + 3) * 64 + om];
#pragma unroll
        for (int r = 0; r < 8; r++) {
            float4 xv = *(const float4*)&xbase[r * 64 + i];
            acc[r][0] += xv.x * wv0.x; acc[r][1] += xv.x * wv0.y; acc[r][2] += xv.x * wv0.z; acc[r][3] += xv.x * wv0.w;
            acc[r][0] += xv.y * wv1.x; acc[r][1] += xv.y * wv1.y; acc[r][2] += xv.y * wv1.z; acc[r][3] += xv.y * wv1.w;
            acc[r][0] += xv.z * wv2.x; acc[r][1] += xv.z * wv2.y; acc[r][2] += xv.z * wv2.z; acc[r][3] += xv.z * wv2.w;
            acc[r][0] += xv.w * wv3.x; acc[r][1] += xv.w * wv3.y; acc[r][2] += xv.w * wv3.z; acc[r][3] += xv.w * wv3.w;
        }
    }

    float4 bias4 = *(const float4*)&b1[om];
    float ls[4] = {0, 0, 0, 0}, lq[4] = {0, 0, 0, 0};
    int bs = bs0 + g;
#pragma unroll
    for (int hh = 0; hh < 8; hh++) {
        float4 v;
        v.x = acc[hh][0] + bias4.x;
        v.y = acc[hh][1] + bias4.y;
        v.z = acc[hh][2] + bias4.z;
        v.w = acc[hh][3] + bias4.w;
        ls[0] += v.x; lq[0] += v.x * v.x;
        ls[1] += v.y; lq[1] += v.y * v.y;
        ls[2] += v.z; lq[2] += v.z * v.z;
        ls[3] += v.w; lq[3] += v.w * v.w;
        *(float4*)&g_y1[(bs * 32 + h8 + hh) * 64 + om] = v;
    }
#pragma unroll
    for (int j = 0; j < 4; j++) {
        atomicAdd(&ssum[om + j], ls[j]);
        atomicAdd(&ssq[om + j],  lq[j]);
    }
    __syncthreads();
    if (t < 64) {
        atomicAdd(&g_sum1[t], ssum[t]);
        atomicAdd(&g_sq1[t],  ssq[t]);
    }
}

// ---------------- conv2: 64->128, 4 centers/block, BOTH halves sequentially -----
// One xs fill; per half: 16KB weight tile, 8x4 tile compute (identical to R14),
// stats + extrema flushed per half. No y2 materialization.
__global__ __launch_bounds__(256, 4) void conv2_kernel(const float* __restrict__ w2,
                                                       const float* __restrict__ b2,
                                                       const float* __restrict__ gam1,
                                                       const float* __restrict__ bet1) {
    extern __shared__ __align__(16) float dsm2[];
    float* wT = dsm2;                         // 64*64 = 4096 floats (half panel)
    float* xs = dsm2 + 4096;                  // 4*32*64 = 8192 floats
    __shared__ float ssum[64], ssq[64];
    __shared__ float s_scale[64], s_shift[64];
    __shared__ unsigned smax[256], smin[256]; // [g 0..3][c 0..63] monotone-encoded

    int t = threadIdx.x;
    int bs0 = blockIdx.x * 4;

    if (t < 64) {
        float mean = g_sum1[t] * (1.0f / NELEM);
        float var  = g_sq1[t] * (1.0f / NELEM) - mean * mean;
        float s = gam1[t] * rsqrtf(var + 1e-5f);
        s_scale[t] = s;
        s_shift[t] = bet1[t] - mean * s;
    }
    __syncthreads();

    const float* Y = &g_y1[bs0 * 2048];
    for (int e = t; e < 8192; e += 256) {
        int i = e & 63;
        float v = Y[e] * s_scale[i] + s_shift[i];
        xs[e] = fmaxf(v, 0.f);
    }

    int om = (t & 15) * 4;
    int hg = t >> 4;                          // 0..15
    int g  = hg >> 2;                         // 0..3 (center)
    int h8 = (hg & 3) * 8;                    // 0,8,16,24
    const float* xbase = &xs[(g * 32 + h8) * 64];

    for (int half = 0; half < 2; half++) {
        int ocb = half * 64;

        // reset smem stats + load this half's weight panel
        if (t < 64) { ssum[t] = 0.f; ssq[t] = 0.f; }
        smax[t] = 0u;
        smin[t] = 0xffffffffu;
        for (int e = t; e < 64 * 64; e += 256) {
            int o = e & 63, i = e >> 6;
            wT[i * 64 + o] = w2[(ocb + o) * 64 + i];
        }
        __syncthreads();

        float acc[8][4];
#pragma unroll
        for (int a = 0; a < 8; a++)
#pragma unroll
            for (int j = 0; j < 4; j++) acc[a][j] = 0.f;

        for (int i = 0; i < 64; i += 4) {
            float4 wv0 = *(const float4*)&wT[(i + 0) * 64 + om];
            float4 wv1 = *(const float4*)&wT[(i + 1) * 64 + om];
            float4 wv2 = *(const float4*)&wT[(i + 2) * 64 + om];
            float4 wv3 = *(const float4*)&wT[(i + 3) * 64 + om];
#pragma unroll
            for (int r = 0; r < 8; r++) {
                float4 xv = *(const float4*)&xbase[r * 64 + i];
                acc[r][0] += xv.x * wv0.x; acc[r][1] += xv.x * wv0.y; acc[r][2] += xv.x * wv0.z; acc[r][3] += xv.x * wv0.w;
                acc[r][0] += xv.y * wv1.x; acc[r][1] += xv.y * wv1.y; acc[r][2] += xv.y * wv1.z; acc[r][3] += xv.y * wv1.w;
                acc[r][0] += xv.z * wv2.x; acc[r][1] += xv.z * wv2.y; acc[r][2] += xv.z * wv2.z; acc[r][3] += xv.z * wv2.w;
                acc[r][0] += xv.w * wv3.x; acc[r][1] += xv.w * wv3.y; acc[r][2] += xv.w * wv3.z; acc[r][3] += xv.w * wv3.w;
            }
        }

        float4 bias4 = *(const float4*)&b2[ocb + om];
        float ls[4] = {0, 0, 0, 0}, lq[4] = {0, 0, 0, 0};
        float vmx[4] = {-3.4e38f, -3.4e38f, -3.4e38f, -3.4e38f};
        float vmn[4] = { 3.4e38f,  3.4e38f,  3.4e38f,  3.4e38f};
#pragma unroll
        for (int hh = 0; hh < 8; hh++) {
            float4 v;
            v.x = acc[hh][0] + bias4.x;
            v.y = acc[hh][1] + bias4.y;
            v.z = acc[hh][2] + bias4.z;
            v.w = acc[hh][3] + bias4.w;
            ls[0] += v.x; lq[0] += v.x * v.x;
            ls[1] += v.y; lq[1] += v.y * v.y;
            ls[2] += v.z; lq[2] += v.z * v.z;
            ls[3] += v.w; lq[3] += v.w * v.w;
            vmx[0] = fmaxf(vmx[0], v.x); vmn[0] = fminf(vmn[0], v.x);
            vmx[1] = fmaxf(vmx[1], v.y); vmn[1] = fminf(vmn[1], v.y);
            vmx[2] = fmaxf(vmx[2], v.z); vmn[2] = fminf(vmn[2], v.z);
            vmx[3] = fmaxf(vmx[3], v.w); vmn[3] = fminf(vmn[3], v.w);
        }
#pragma unroll
        for (int j = 0; j < 4; j++) {
            atomicAdd(&ssum[om + j], ls[j]);
            atomicAdd(&ssq[om + j],  lq[j]);
            atomicMax(&smax[g * 64 + om + j], enc_mono(vmx[j]));
            atomicMin(&smin[g * 64 + om + j], enc_mono(vmn[j]));
        }
        __syncthreads();

        if (t < 64) {
            atomicAdd(&g_sum2[ocb + t], ssum[t]);
            atomicAdd(&g_sq2[ocb + t],  ssq[t]);
        }
        {
            int gg = t >> 6, cc = t & 63;
            int bs = bs0 + gg;
            g_ymax[bs * 128 + ocb + cc] = dec_mono(smax[gg * 64 + cc]);
            g_ymin[bs * 128 + ocb + cc] = dec_mono(smin[gg * 64 + cc]);
        }
        __syncthreads();                      // stats read before next-half reset
    }
}

// ---------------- final: BN2 on pooled extrema + relu + poscopy -----------------
__global__ __launch_bounds__(256) void finalpool_kernel(float* __restrict__ out,
                                                        const float* __restrict__ gam2,
                                                        const float* __restrict__ bet2) {
    __shared__ float s_sc[128], s_sh[128];
    int t = threadIdx.x;
    if (t < 128) {
        float mean = g_sum2[t] * (1.0f / NELEM);
        float var  = g_sq2[t] * (1.0f / NELEM) - mean * mean;
        float s = gam2[t] * rsqrtf(var + 1e-5f);
        s_sc[t] = s;
        s_sh[t] = bet2[t] - mean * s;
    }
    __syncthreads();

    int gwarp = (blockIdx.x * blockDim.x + t) >> 5;   // bs
    int lane = t & 31;
    {
        int bs = gwarp;
        int b = bs >> 10, s = bs & 1023;
        const float* MX = &g_ymax[bs * 128];
        const float* MN = &g_ymin[bs * 128];
        float* F = out + Bb * 3 * Ss + b * 128 * Ss + s;
#pragma unroll
        for (int j = 0; j < 4; j++) {
            int c = lane + 32 * j;
            float scl = s_sc[c], sft = s_sh[c];
            float y = (scl >= 0.f) ? MX[c] : MN[c];
            float v = fmaxf(y * scl + sft, 0.f);
            F[c * Ss] = v;
        }
    }

    // fused poscopy: first 24576 global threads copy pos_out
    int e = blockIdx.x * blockDim.x + t;
    if (e < Bb * 3 * Ss) {
        int b2_ = e / (3 * Ss);
        int r = e - b2_ * (3 * Ss);
        int c = r / Ss;
        int s2 = r - c * Ss;
        out[e] = g_centers[(b2_ * Ss + s2) * 3 + c];
    }
}

// ---------------- launch --------------------------------------------------------
extern "C" void kernel_launch(void* const* d_in, const int* in_sizes, int n_in,
                              void* d_out, int out_size) {
    const float* pos  = (const float*)d_in[0];
    const float* feat = (const float*)d_in[1];
    const float* w0   = (const float*)d_in[2];
    const float* b0   = (const float*)d_in[3];
    const float* g0   = (const float*)d_in[4];
    const float* be0  = (const float*)d_in[5];
    const float* w1   = (const float*)d_in[6];
    const float* b1   = (const float*)d_in[7];
    const float* g1   = (const float*)d_in[8];
    const float* be1  = (const float*)d_in[9];
    const float* w2   = (const float*)d_in[10];
    const float* b2   = (const float*)d_in[11];
    const float* g2   = (const float*)d_in[12];
    const float* be2  = (const float*)d_in[13];
    float* out = (float*)d_out;

    const int FUSED_DYN = (3 * Nn + 67 * 64 + 4 * 32 * 68) * (int)sizeof(float); // 101120
    const int CV_DYN = (64 * 64 + 4 * 32 * 64) * (int)sizeof(float);             // 49152
    cudaFuncSetAttribute(fused_kernel, cudaFuncAttributeMaxDynamicSharedMemorySize, FUSED_DYN);
    cudaFuncSetAttribute(conv1_kernel, cudaFuncAttributeMaxDynamicSharedMemorySize, CV_DYN);
    cudaFuncSetAttribute(conv2_kernel, cudaFuncAttributeMaxDynamicSharedMemorySize, CV_DYN);

    zero_stats_kernel<<<1, 128>>>();                              // 1
    fused_kernel<<<148, 512, FUSED_DYN>>>(pos, feat, w0, b0);     // 2
    conv1_kernel<<<Bb * Ss / 4, 256, CV_DYN>>>(w1, b1, g0, be0);  // 3
    conv2_kernel<<<Bb * Ss / 4, 256, CV_DYN>>>(w2, b2, g1, be1);  // 4
    finalpool_kernel<<<Bb * Ss / 8, 256>>>(out, g2, be2);         // 5
}